// round 1
// baseline (speedup 1.0000x reference)
#include <cuda_runtime.h>
#include <math.h>

// Problem constants
#define NB 8        // basic
#define NM 4        // mixed (output heads)
#define NF 128      // frames (S)
#define NN 25       // nodes
#define NT 255      // 2F-1
#define DD 3201     // 1 + NN*NF
#define INNER 3200  // NN*NF
#define PROW 6375   // NT*NN  (per (h,n) table row)
#define ROWS_PER_BLK 16
#define WINLEN 3575 // (ROWS_PER_BLK-1)*25 + INNER

// Scratch (static device globals — no allocation)
static __device__ __align__(16) float g_g[NM * NT * NB];     // [h][t][b]
static __device__ __align__(16) float g_P2[NM * NN * PROW];  // [h][n][t*25+m]
static __device__ float g_dvec[NM * DD];                     // [h][r]

// ---------------- K1: g[h][t][b] = W[h,b] * sigmoid(te[b,t]) ----------------
__global__ void pm_k_g(const float* __restrict__ te, const float* __restrict__ W) {
    __shared__ float ce[NB * NT];
    for (int idx = threadIdx.x; idx < NB * NT; idx += blockDim.x)
        ce[idx] = 1.0f / (1.0f + expf(-te[idx]));
    __syncthreads();
    for (int idx = threadIdx.x; idx < NM * NT * NB; idx += blockDim.x) {
        int b = idx & 7;
        int t = (idx >> 3) % NT;
        int h = idx / (NT * 8);
        g_g[idx] = W[h * NB + b] * ce[b * NT + t];
    }
}

// ---------------- K2: P2[h][n][t*25+m] = relu(bias[h] + sum_b g*mat) --------
__global__ void pm_k_p2(const float* __restrict__ mat, const float* __restrict__ bias) {
    int h = blockIdx.x / NN, n = blockIdx.x % NN;
    __shared__ float matsh[NB * NN];  // [b][m]
    for (int idx = threadIdx.x; idx < NB * NN; idx += blockDim.x)
        matsh[idx] = mat[(idx / NN) * NN * NN + n * NN + (idx % NN)];
    __syncthreads();
    float bh = bias[h];
    float* dst = &g_P2[(h * NN + n) * PROW];
    for (int e = threadIdx.x; e < PROW; e += blockDim.x) {
        int t = e / NN, m = e - t * NN;
        const float4* gp = reinterpret_cast<const float4*>(&g_g[(h * NT + t) * NB]);
        float4 g0 = gp[0], g1 = gp[1];
        float acc = bh;
        acc += g0.x * matsh[0 * NN + m] + g0.y * matsh[1 * NN + m] +
               g0.z * matsh[2 * NN + m] + g0.w * matsh[3 * NN + m];
        acc += g1.x * matsh[4 * NN + m] + g1.y * matsh[5 * NN + m] +
               g1.z * matsh[6 * NN + m] + g1.w * matsh[7 * NN + m];
        dst[e] = fmaxf(acc, 0.0f);
    }
}

// ---------------- block reduce helper ----------------
__device__ __forceinline__ float pm_block_reduce(float v, float* red) {
    #pragma unroll
    for (int o = 16; o; o >>= 1) v += __shfl_down_sync(0xffffffffu, v, o);
    int wid = threadIdx.x >> 5, lane = threadIdx.x & 31;
    if (lane == 0) red[wid] = v;
    __syncthreads();
    if (wid == 0) {
        v = (lane < 8) ? red[lane] : 0.0f;
        #pragma unroll
        for (int o = 4; o; o >>= 1) v += __shfl_down_sync(0xffffffffu, v, o);
    }
    return v;  // valid on thread 0
}

// ---------------- K3: row sums -> g_dvec --------------------------------
// grid: 800 chunk blocks (h, n, i-chunk of 16) + 4 row-0 blocks; 256 threads.
__global__ __launch_bounds__(256) void pm_k_rowsum(const float* __restrict__ minit) {
    __shared__ float shp[WINLEN];
    __shared__ float red[8];
    int bid = blockIdx.x;
    if (bid >= 800) {
        int h = bid - 800;
        const float* m0 = &minit[(size_t)h * DD * DD];
        float s = 0.0f;
        for (int c = threadIdx.x; c < DD; c += 256) s += m0[c];
        s = pm_block_reduce(s, red);
        if (threadIdx.x == 0) g_dvec[h * DD] = rsqrtf(fmaxf(s, 1.0f));
        return;
    }
    int h = bid / 200;
    int rest = bid % 200;
    int n = rest / 8;
    int i0 = (rest % 8) * ROWS_PER_BLK;
    const float* psrc = &g_P2[(h * NN + n) * PROW + (112 - i0) * 25];
    for (int e = threadIdx.x; e < WINLEN; e += 256) shp[e] = psrc[e];
    __syncthreads();
    bool masked = (n == NN - 1);
    for (int ii = 0; ii < ROWS_PER_BLK; ii++) {
        int i = i0 + ii;
        const float* prow = &shp[(ROWS_PER_BLK - 1 - ii) * 25];
        float s = 0.0f;
        for (int cc = threadIdx.x; cc < INNER; cc += 256) {
            float v = prow[cc];
            if (masked) {
                int jj = cc / 25, m = cc - jj * 25;
                if (!(m == 24 || jj == i)) v = 0.0f;
            }
            s += v;
        }
        s = pm_block_reduce(s, red);
        if (threadIdx.x == 0) {
            int r = 1 + i * 25 + n;
            float c0 = minit[((size_t)h * DD + r) * DD];  // column-0 init value
            g_dvec[h * DD + r] = rsqrtf(fmaxf(s + c0, 1.0f));
        }
        __syncthreads();
    }
}

// ---------------- K4: write output -------------------------------------
// grid: 4 row-0 blocks + 800 chunk blocks; 256 threads.
__global__ __launch_bounds__(256) void pm_k_out(const float* __restrict__ minit,
                                               float* __restrict__ out) {
    __shared__ float sh_dv[DD];
    __shared__ float sh_p[WINLEN];
    int bid = blockIdx.x;
    if (bid < 4) {
        int h = bid;
        float d0 = g_dvec[h * DD];
        const float* dv = &g_dvec[h * DD];
        const float* m0 = &minit[(size_t)h * DD * DD];
        float* o = &out[(size_t)h * DD * DD];
        for (int c = threadIdx.x; c < DD; c += 256)
            o[c] = m0[c] * d0 * dv[c];
        return;
    }
    int b2 = bid - 4;
    int h = b2 / 200;
    int rest = b2 % 200;
    int n = rest / 8;
    int i0 = (rest % 8) * ROWS_PER_BLK;

    for (int c = threadIdx.x; c < DD; c += 256) sh_dv[c] = g_dvec[h * DD + c];
    const float* psrc = &g_P2[(h * NN + n) * PROW + (112 - i0) * 25];
    for (int e = threadIdx.x; e < WINLEN; e += 256) sh_p[e] = psrc[e];
    __syncthreads();

    float d0 = sh_dv[0];
    bool masked = (n == NN - 1);
    for (int ii = 0; ii < ROWS_PER_BLK; ii++) {
        int i = i0 + ii;
        int r = 1 + i * 25 + n;
        float dr = sh_dv[r];
        float c0v = minit[((size_t)h * DD + r) * DD];  // 0.5 by construction
        float* o = &out[((size_t)h * DD + r) * DD];
        const float* prow = &sh_p[(ROWS_PER_BLK - 1 - ii) * 25];
        if (threadIdx.x == 0) o[0] = c0v * dr * d0;
        #pragma unroll 4
        for (int c = 1 + threadIdx.x; c < DD; c += 256) {
            int cc = c - 1;
            float v = prow[cc];
            if (masked) {
                int jj = cc / 25, m = cc - jj * 25;
                if (!(m == 24 || jj == i)) v = 0.0f;
            }
            o[c] = v * dr * sh_dv[c];
        }
    }
}

extern "C" void kernel_launch(void* const* d_in, const int* in_sizes, int n_in,
                              void* d_out, int out_size) {
    const float* mat   = (const float*)d_in[0];  // (8,25,25)
    const float* te    = (const float*)d_in[1];  // (8,255)
    const float* W     = (const float*)d_in[2];  // (4,8)
    const float* bias  = (const float*)d_in[3];  // (4,)
    const float* minit = (const float*)d_in[4];  // (4,3201,3201)
    float* out = (float*)d_out;

    pm_k_g<<<1, 1024>>>(te, W);
    pm_k_p2<<<NM * NN, 256>>>(mat, bias);
    pm_k_rowsum<<<804, 256>>>(minit);
    pm_k_out<<<804, 256>>>(minit, out);
}

// round 4
// speedup vs baseline: 1.6627x; 1.6627x over previous
#include <cuda_runtime.h>
#include <math.h>

#define NB 8
#define NM 4
#define NN 25
#define NT 255
#define DD 3201
#define INNER 3200
#define PROW 6375          // NT*NN, per (h,n) table row
#define RPB 8              // rows per k_out block
#define WLEN 3375          // (RPB-1)*25 + INNER

// scratch (static device globals — no allocation)
static __device__ __align__(16) float g_P2[NM * NN * PROW];
static __device__ float g_dvec[NM * DD];

__device__ __forceinline__ float warp_iscan(float v) {
    int lane = threadIdx.x & 31;
    #pragma unroll
    for (int o = 1; o < 32; o <<= 1) {
        float u = __shfl_up_sync(0xffffffffu, v, o);
        if (lane >= o) v += u;
    }
    return v;
}

// ---------------- K1: fused g + P2 + prefix-scan row sums + d --------------
// grid: 100 (h,n) blocks + 4 row-0 blocks; 256 threads.
__global__ __launch_bounds__(256) void pm_k_main(
    const float* __restrict__ mat, const float* __restrict__ te,
    const float* __restrict__ W, const float* __restrict__ bias,
    const float* __restrict__ minit)
{
    __shared__ __align__(16) float sh[PROW + 1];  // P2 row (+pad keeps gsh 16B-aligned)
    __shared__ __align__(16) float gsh[NT * NB];  // g[t][b]  (float4-loaded)
    __shared__ float matsh[NB * NN];  // mat[b][n][m] slice
    __shared__ float P[256];          // exclusive prefix of chunk sums
    __shared__ float Q[256];          // exclusive prefix of col-24 values
    __shared__ float wA[8], wB[8], wAo[8], wBo[8];
    __shared__ float s_c127, s_v127;

    int bid = blockIdx.x;
    int tid = threadIdx.x;
    int lane = tid & 31, wid = tid >> 5;

    if (bid >= 100) {                 // row-0 degree: sum of minit row 0
        int h = bid - 100;
        const float* m0 = minit + (size_t)h * DD * DD;
        float s = 0.0f;
        for (int c = tid; c < DD; c += 256) s += m0[c];
        #pragma unroll
        for (int o = 16; o; o >>= 1) s += __shfl_down_sync(0xffffffffu, s, o);
        if (lane == 0) wA[wid] = s;
        __syncthreads();
        if (wid == 0) {
            s = (lane < 8) ? wA[lane] : 0.0f;
            #pragma unroll
            for (int o = 4; o; o >>= 1) s += __shfl_down_sync(0xffffffffu, s, o);
            if (lane == 0) g_dvec[h * DD] = rsqrtf(fmaxf(s, 1.0f));
        }
        return;
    }

    int h = bid / NN, n = bid % NN;

    // g[t][b] = W[h,b] * sigmoid(te[b,t])
    for (int idx = tid; idx < NT * NB; idx += 256) {
        int b = idx & 7, t = idx >> 3;
        gsh[idx] = W[h * NB + b] / (1.0f + expf(-te[b * NT + t]));
    }
    // mat slice [b][m] for this n
    for (int idx = tid; idx < NB * NN; idx += 256)
        matsh[idx] = mat[(idx / NN) * NN * NN + n * NN + (idx % NN)];
    __syncthreads();

    // each thread t < 255 computes chunk t (25 elems) of the P2 row,
    // accumulating its chunk sum (a) and capturing the m==24 value (b)
    float a = 0.0f, b = 0.0f;
    if (tid < NT) {
        float bh = bias[h];
        const float4* gp = reinterpret_cast<const float4*>(gsh + tid * NB);
        float4 g0 = gp[0], g1 = gp[1];
        int base = tid * NN;
        #pragma unroll
        for (int m = 0; m < NN; m++) {
            float acc = bh;
            acc += g0.x * matsh[0 * NN + m] + g0.y * matsh[1 * NN + m] +
                   g0.z * matsh[2 * NN + m] + g0.w * matsh[3 * NN + m];
            acc += g1.x * matsh[4 * NN + m] + g1.y * matsh[5 * NN + m] +
                   g1.z * matsh[6 * NN + m] + g1.w * matsh[7 * NN + m];
            float v = fmaxf(acc, 0.0f);
            sh[base + m] = v;
            a += v;
            if (m == NN - 1) b = v;
        }
    }
    if (tid == 127) { s_c127 = a; s_v127 = b; }

    // dual inclusive scan over 256 thread values (thread 255 contributes 0)
    float ia = warp_iscan(a);
    float ib = warp_iscan(b);
    if (lane == 31) { wA[wid] = ia; wB[wid] = ib; }
    __syncthreads();
    if (tid == 0) {
        float sa = 0.0f, sb = 0.0f;
        #pragma unroll
        for (int w = 0; w < 8; w++) { wAo[w] = sa; wBo[w] = sb; sa += wA[w]; sb += wB[w]; }
    }
    __syncthreads();
    P[tid] = ia - a + wAo[wid];   // exclusive prefix
    Q[tid] = ib - b + wBo[wid];

    // write P2 row to global (coalesced)
    float* dst = g_P2 + (size_t)(h * NN + n) * PROW;
    for (int e = tid; e < PROW; e += 256) dst[e] = sh[e];
    __syncthreads();

    // row degrees for rows r = 1 + i*25 + n
    if (tid < 128) {
        int i = tid;
        int r = 1 + i * NN + n;
        float c0 = minit[(size_t)(h * DD + r) * DD];
        float sum;
        if (n == NN - 1)
            sum = (Q[255 - i] - Q[127 - i]) + s_c127 - s_v127;
        else
            sum = P[255 - i] - P[127 - i];
        g_dvec[h * DD + r] = rsqrtf(fmaxf(sum + c0, 1.0f));
    }
}

// ---------------- K2: write output (vectorized) ----------------------------
// grid: 4 row-0 blocks + 1600 chunk blocks; 256 threads.
__global__ __launch_bounds__(256) void pm_k_out(const float* __restrict__ minit,
                                                float* __restrict__ out)
{
    __shared__ float dv[DD];
    __shared__ float shp[WLEN + 1];   // +1 pad so p[0] stays in-bounds
    int bid = blockIdx.x;
    int tid = threadIdx.x;

    if (bid < 4) {
        int h = bid;
        const float* m0 = minit + (size_t)h * DD * DD;
        const float* dvp = g_dvec + h * DD;
        float d0 = dvp[0];
        float* o = out + (size_t)h * DD * DD;
        for (int c = tid; c < DD; c += 256)
            o[c] = m0[c] * d0 * dvp[c];
        return;
    }
    int b2 = bid - 4;
    int h = b2 / 400;
    int rest = b2 % 400;
    int n = rest / 16;
    int chunk = rest % 16;
    int i0 = chunk * RPB;

    for (int c = tid; c < DD; c += 256) dv[c] = g_dvec[h * DD + c];
    const float* src = g_P2 + (size_t)(h * NN + n) * PROW + (120 - i0) * NN;
    for (int e = tid; e < WLEN; e += 256) shp[e + 1] = src[e];
    __syncthreads();

    float d0 = dv[0];
    bool masked = (n == NN - 1);

    for (int ii = 0; ii < RPB; ii++) {
        int i = i0 + ii;
        int r = 1 + i * NN + n;
        float dr = dv[r];
        float c0v = minit[(size_t)(h * DD + r) * DD];
        float* o = out + (size_t)(h * DD + r) * DD;
        // p[c] = window value for output col c (c>=1): shp[1 + rowoff + c-1]
        const float* p = shp + (RPB - 1 - ii) * NN;

        int a0 = (int)(((16u - ((unsigned)(size_t)o & 15u)) & 15u) >> 2);
        int nv = (DD - a0) >> 2;
        int ct = a0 + (nv << 2);
        unsigned ib = (unsigned)(i * NN);

        if (!masked) {
            for (int c = tid; c < a0; c += 256)
                o[c] = ((c == 0) ? c0v * d0 : p[c] * dv[c]) * dr;
            for (int k = tid; k < nv; k += 256) {
                int c = a0 + (k << 2);
                float4 w;
                w.x = ((c == 0) ? c0v * d0 : p[c] * dv[c]) * dr;
                w.y = p[c + 1] * dv[c + 1] * dr;
                w.z = p[c + 2] * dv[c + 2] * dr;
                w.w = p[c + 3] * dv[c + 3] * dr;
                *reinterpret_cast<float4*>(o + c) = w;
            }
            for (int c = ct + tid; c < DD; c += 256)
                o[c] = ((c == 0) ? c0v * d0 : p[c] * dv[c]) * dr;
        } else {
            for (int c = tid; c < a0; c += 256) {
                float v;
                if (c == 0) v = c0v * d0;
                else {
                    unsigned cc = (unsigned)(c - 1);
                    bool keep = (cc % 25u == 24u) || ((cc - ib) < 25u);
                    v = keep ? p[c] * dv[c] : 0.0f;
                }
                o[c] = v * dr;
            }
            for (int k = tid; k < nv; k += 256) {
                int c = a0 + (k << 2);
                float4 w;
                {
                    float v;
                    if (c == 0) v = c0v * d0;
                    else {
                        unsigned cc = (unsigned)(c - 1);
                        bool keep = (cc % 25u == 24u) || ((cc - ib) < 25u);
                        v = keep ? p[c] * dv[c] : 0.0f;
                    }
                    w.x = v * dr;
                }
                #pragma unroll
                for (int l = 1; l < 4; l++) {
                    int c2 = c + l;
                    unsigned cc = (unsigned)(c2 - 1);
                    bool keep = (cc % 25u == 24u) || ((cc - ib) < 25u);
                    float v = keep ? p[c2] * dv[c2] : 0.0f;
                    (&w.x)[l] = v * dr;
                }
                *reinterpret_cast<float4*>(o + c) = w;
            }
            for (int c = ct + tid; c < DD; c += 256) {
                float v;
                if (c == 0) v = c0v * d0;
                else {
                    unsigned cc = (unsigned)(c - 1);
                    bool keep = (cc % 25u == 24u) || ((cc - ib) < 25u);
                    v = keep ? p[c] * dv[c] : 0.0f;
                }
                o[c] = v * dr;
            }
        }
    }
}

extern "C" void kernel_launch(void* const* d_in, const int* in_sizes, int n_in,
                              void* d_out, int out_size) {
    const float* mat   = (const float*)d_in[0];  // (8,25,25)
    const float* te    = (const float*)d_in[1];  // (8,255)
    const float* W     = (const float*)d_in[2];  // (4,8)
    const float* bias  = (const float*)d_in[3];  // (4,)
    const float* minit = (const float*)d_in[4];  // (4,3201,3201)
    float* out = (float*)d_out;

    pm_k_main<<<104, 256>>>(mat, te, W, bias, minit);
    pm_k_out<<<1604, 256>>>(minit, out);
}

// round 5
// speedup vs baseline: 2.0792x; 1.2506x over previous
#include <cuda_runtime.h>
#include <math.h>

#define NB 8
#define NM 4
#define NN 25
#define NT 255
#define DD 3201
#define INNER 3200
#define PROW 6375          // NT*NN, per (h,n) table row
#define WSPAN 4700         // (60)*25 + 3200 : window span for 16 rows spaced 4
#define SHPSZ 4708         // WSPAN + 3 (sigma) + pad

// scratch (static device globals — no allocation)
static __device__ __align__(16) float g_P2[NM * NN * PROW];
static __device__ float g_dvec[NM * DD];

__device__ __forceinline__ float warp_iscan(float v) {
    int lane = threadIdx.x & 31;
    #pragma unroll
    for (int o = 1; o < 32; o <<= 1) {
        float u = __shfl_up_sync(0xffffffffu, v, o);
        if (lane >= o) v += u;
    }
    return v;
}

// ---------------- K1: fused g + P2 + prefix-scan row sums + d --------------
// grid: 100 (h,n) blocks + 4 row-0 blocks; 256 threads.
__global__ __launch_bounds__(256) void pm_k_main(
    const float* __restrict__ mat, const float* __restrict__ te,
    const float* __restrict__ W, const float* __restrict__ bias,
    const float* __restrict__ minit)
{
    __shared__ __align__(16) float sh[PROW + 1];
    __shared__ __align__(16) float gsh[NT * NB];
    __shared__ float matsh[NB * NN];
    __shared__ float P[256];
    __shared__ float Q[256];
    __shared__ float wA[8], wB[8], wAo[8], wBo[8];
    __shared__ float s_c127, s_v127;

    int bid = blockIdx.x;
    int tid = threadIdx.x;
    int lane = tid & 31, wid = tid >> 5;

    if (bid >= 100) {                 // row-0 degree: sum of minit row 0
        int h = bid - 100;
        const float* m0 = minit + (size_t)h * DD * DD;
        float s = 0.0f;
        for (int c = tid; c < DD; c += 256) s += m0[c];
        #pragma unroll
        for (int o = 16; o; o >>= 1) s += __shfl_down_sync(0xffffffffu, s, o);
        if (lane == 0) wA[wid] = s;
        __syncthreads();
        if (wid == 0) {
            s = (lane < 8) ? wA[lane] : 0.0f;
            #pragma unroll
            for (int o = 4; o; o >>= 1) s += __shfl_down_sync(0xffffffffu, s, o);
            if (lane == 0) g_dvec[h * DD] = rsqrtf(fmaxf(s, 1.0f));
        }
        return;
    }

    int h = bid / NN, n = bid % NN;

    for (int idx = tid; idx < NT * NB; idx += 256) {
        int b = idx & 7, t = idx >> 3;
        gsh[idx] = W[h * NB + b] / (1.0f + expf(-te[b * NT + t]));
    }
    for (int idx = tid; idx < NB * NN; idx += 256)
        matsh[idx] = mat[(idx / NN) * NN * NN + n * NN + (idx % NN)];
    __syncthreads();

    float a = 0.0f, b = 0.0f;
    if (tid < NT) {
        float bh = bias[h];
        const float4* gp = reinterpret_cast<const float4*>(gsh + tid * NB);
        float4 g0 = gp[0], g1 = gp[1];
        int base = tid * NN;
        #pragma unroll
        for (int m = 0; m < NN; m++) {
            float acc = bh;
            acc += g0.x * matsh[0 * NN + m] + g0.y * matsh[1 * NN + m] +
                   g0.z * matsh[2 * NN + m] + g0.w * matsh[3 * NN + m];
            acc += g1.x * matsh[4 * NN + m] + g1.y * matsh[5 * NN + m] +
                   g1.z * matsh[6 * NN + m] + g1.w * matsh[7 * NN + m];
            float v = fmaxf(acc, 0.0f);
            sh[base + m] = v;
            a += v;
            if (m == NN - 1) b = v;
        }
    }
    if (tid == 127) { s_c127 = a; s_v127 = b; }

    float ia = warp_iscan(a);
    float ib = warp_iscan(b);
    if (lane == 31) { wA[wid] = ia; wB[wid] = ib; }
    __syncthreads();
    if (tid == 0) {
        float sa = 0.0f, sb = 0.0f;
        #pragma unroll
        for (int w = 0; w < 8; w++) { wAo[w] = sa; wBo[w] = sb; sa += wA[w]; sb += wB[w]; }
    }
    __syncthreads();
    P[tid] = ia - a + wAo[wid];
    Q[tid] = ib - b + wBo[wid];

    float* dst = g_P2 + (size_t)(h * NN + n) * PROW;
    for (int e = tid; e < PROW; e += 256) dst[e] = sh[e];
    __syncthreads();

    if (tid < 128) {
        int i = tid;
        int r = 1 + i * NN + n;
        float c0 = minit[(size_t)(h * DD + r) * DD];
        float sum;
        if (n == NN - 1)
            sum = (Q[255 - i] - Q[127 - i]) + s_c127 - s_v127;
        else
            sum = P[255 - i] - P[127 - i];
        g_dvec[h * DD + r] = rsqrtf(fmaxf(sum + c0, 1.0f));
    }
}

// ---------------- K2: output, phase-grouped rows, all-LDS.128 --------------
// grid: 4 row-0 blocks + 800 blocks (h,n,g=i%4,half); 256 threads; 16 rows/blk
__global__ __launch_bounds__(256) void pm_k_out(const float* __restrict__ minit,
                                                float* __restrict__ out)
{
    __shared__ __align__(16) float shp[SHPSZ];
    __shared__ __align__(16) float dvr[3208];   // rotated dv copy
    int bid = blockIdx.x;
    int tid = threadIdx.x;

    if (bid < 4) {
        int h = bid;
        const float* m0 = minit + (size_t)h * DD * DD;
        const float* dvp = g_dvec + h * DD;
        float d0 = dvp[0];
        float* o = out + (size_t)h * DD * DD;
        for (int c = tid; c < DD; c += 256)
            o[c] = m0[c] * d0 * dvp[c];
        return;
    }
    int b2 = bid - 4;
    int h = b2 / 200;
    int rest = b2 % 200;
    int n = rest / 8;
    int sub = rest % 8;
    int g = sub & 3;
    int half = sub >> 2;
    int i_min = g + 64 * half;

    int r0 = 1 + i_min * NN + n;
    int a0 = (4 - ((h + r0) & 3)) & 3;          // head floats to 16B boundary
    int sigma = (1 - a0) & 3;                   // window stage shift
    int E0 = (67 - i_min) * NN;                 // window start in P2 row
    bool masked = (n == NN - 1);

    const float* dvh = g_dvec + h * DD;
    const float* src = g_P2 + (size_t)(h * NN + n) * PROW + E0;
    for (int e = tid; e < WSPAN; e += 256) shp[e + sigma] = src[e];
    if (!masked)
        for (int x = tid; x < DD - a0; x += 256) dvr[x] = dvh[x + a0];
    __syncthreads();

    float d0 = dvh[0];
    int nv = (DD - a0) >> 2;
    int ct = a0 + (nv << 2);
    int sb_extra = (a0 >= 2) ? 4 : 0;           // (sigma + a0 - 1) is 0 or 4

    if (!masked) {
        for (int jj = 0; jj < 16; jj++) {
            int i = i_min + 4 * jj;
            int r = 1 + i * NN + n;
            float dr = dvh[r];
            float c0v = minit[(size_t)(h * DD + r) * DD];
            float* o = out + (size_t)(h * DD + r) * DD;
            int Sbase = (60 - 4 * jj) * NN + sb_extra;     // ≡0 mod 4
            int Ssc = (60 - 4 * jj) * NN + sigma - 1;      // scalar p index base (+c)

            // head (c < a0), includes c==0 when a0>0
            if (tid < a0) {
                int c = tid;
                float v = (c == 0) ? c0v * d0 : shp[Ssc + c] * dvh[c];
                o[c] = v * dr;
            }
            // vector body
            for (int k = tid; k < nv; k += 256) {
                const float4 pv = *reinterpret_cast<const float4*>(shp + Sbase + (k << 2));
                const float4 dq = *reinterpret_cast<const float4*>(dvr + (k << 2));
                float4 w;
                w.x = pv.x * dq.x * dr;
                w.y = pv.y * dq.y * dr;
                w.z = pv.z * dq.z * dr;
                w.w = pv.w * dq.w * dr;
                if (a0 == 0 && k == 0) w.x = c0v * d0 * dr;
                *reinterpret_cast<float4*>(o + a0 + (k << 2)) = w;
            }
            // tail
            for (int c = ct + tid; c < DD; c += 256)
                o[c] = shp[Ssc + c] * dvh[c] * dr;
        }
    } else {
        // pass 1: zeros (vectorized), with c==0 value
        for (int jj = 0; jj < 16; jj++) {
            int i = i_min + 4 * jj;
            int r = 1 + i * NN + n;
            float dr = dvh[r];
            float c0v = minit[(size_t)(h * DD + r) * DD];
            float* o = out + (size_t)(h * DD + r) * DD;
            if (tid < a0) o[tid] = (tid == 0) ? c0v * d0 * dr : 0.0f;
            float4 z = make_float4(0.f, 0.f, 0.f, 0.f);
            for (int k = tid; k < nv; k += 256) {
                float4 w = z;
                if (a0 == 0 && k == 0) w.x = c0v * d0 * dr;
                *reinterpret_cast<float4*>(o + a0 + (k << 2)) = w;
            }
            for (int c = ct + tid; c < DD; c += 256) o[c] = 0.0f;
        }
        __syncthreads();
        // pass 2: scatter 152 nonzeros per row (train + diagonal block)
        for (int jj = 0; jj < 16; jj++) {
            int i = i_min + 4 * jj;
            int r = 1 + i * NN + n;
            float dr = dvh[r];
            float* o = out + (size_t)(h * DD + r) * DD;
            int Ssc = (60 - 4 * jj) * NN + sigma - 1;
            if (tid < 128) {
                int c = 25 * (tid + 1);            // cc%25==24 train
                o[c] = shp[Ssc + c] * dvh[c] * dr;
            } else if (tid < 152) {
                int m = tid - 128;                 // diagonal block, m=0..23
                int c = 1 + i * NN + m;
                o[c] = shp[Ssc + c] * dvh[c] * dr;
            }
        }
    }
}

extern "C" void kernel_launch(void* const* d_in, const int* in_sizes, int n_in,
                              void* d_out, int out_size) {
    const float* mat   = (const float*)d_in[0];  // (8,25,25)
    const float* te    = (const float*)d_in[1];  // (8,255)
    const float* W     = (const float*)d_in[2];  // (4,8)
    const float* bias  = (const float*)d_in[3];  // (4,)
    const float* minit = (const float*)d_in[4];  // (4,3201,3201)
    float* out = (float*)d_out;

    pm_k_main<<<104, 256>>>(mat, te, W, bias, minit);
    pm_k_out<<<804, 256>>>(minit, out);
}